// round 16
// baseline (speedup 1.0000x reference)
#include <cuda_runtime.h>
#include <math.h>

// ---------------- dimensions ----------------
#define NB 8          // batch*groups
#define S  66
#define S2 4356       // 66*66
#define S3 287496     // 66^3
#define HH 33
#define H2 1089       // 33*33
#define H3 35937      // 33^3
#define D3 262144     // 64^3

// output packing offsets (x, helmholtz, vel, vel_phi, vel_vort)
#define OFF_X     0
#define OFF_HELM  16777216
#define OFF_VEL   25977088
#define OFF_VPHI  32268544
#define OFF_VVORT 38560000

#define WC1_PACK 7776          // 18*27*16
#define NBLK1 375              // conv1 blocks: ceil(NB*33*33*11/256)
#define NBLK2 2995             // conv2 blocks: ceil(NB*66*66*22/256)
#define ENC_BPN 562            // ceil(H3/64)

// ---------------- scratch (static device memory; no allocation APIs) ----------------
__device__ float g_f[3][NB*64*H3];     // encoder outputs: pm, pb, nm
__device__ float g_corr[NB*18*H3];     // correlation output (18 distinct channels)
__device__ float g_c1[NB*16*H3];       // conv1 raw out (phi 0-7, vort 8-15)
__device__ float g_u1[NB*16*S3];       // upsampled (post BN1+relu)
__device__ float g_c2[NB*16*S3];       // conv2 raw out
__device__ float g_phi1[64*D3];        // advect pass 1
__device__ float g_comb[64*D3];        // 1.5*tex - 0.5*phi2
__device__ float g_pred[64*D3];        // final advect result
__device__ float g_wc1[3*WC1_PACK];    // conv1 summed packs
__device__ float g_wp2[27*8*16];       // packed conv2 weights
__device__ float g_stat[64];           // mean1[16], istd1[16], mean2[16], istd2[16]
__device__ double g_pc1[16*NBLK1*2];   // conv1 per-block stat partials
__device__ double g_pc2[16*NBLK2*2];   // conv2 per-block stat partials

// ---------------- packed f32x2 helpers (sm_103a FFMA2 via PTX) ----------------
__device__ __forceinline__ unsigned long long pk2(float a, float b) {
    unsigned long long r;
    asm("mov.b64 %0, {%1, %2};" : "=l"(r) : "f"(a), "f"(b));
    return r;
}
__device__ __forceinline__ void fma2(unsigned long long& d, unsigned long long a, unsigned long long b) {
    asm("fma.rn.f32x2 %0, %1, %2, %0;" : "+l"(d) : "l"(a), "l"(b));
}
__device__ __forceinline__ void upk2(unsigned long long v, float& lo, float& hi) {
    asm("mov.b64 {%0, %1}, %2;" : "=f"(lo), "=f"(hi) : "l"(v));
}
__device__ __forceinline__ float wred(float v) {
#pragma unroll
    for (int o = 16; o > 0; o >>= 1) v += __shfl_down_sync(0xffffffffu, v, o);
    return v;
}

// ---------------- weight packing ----------------
__global__ void pack_kernel(const float* __restrict__ pw1, const float* __restrict__ vw1,
                            const float* __restrict__ pw2, const float* __restrict__ vw2) {
    int i = blockIdx.x * blockDim.x + threadIdx.x;
    if (i < 3*WC1_PACK) {
        int pack = i / WC1_PACK; int r = i % WC1_PACK;
        int oc = r & 15; int t18 = r >> 4; int ic = t18 % 18; int tap = t18 / 18;
        int w = ic / 9, s = ic % 9;
        int c0 = w*27 + s, c1 = c0 + 9, c2 = c0 + 18;
        const float* src = (oc < 8) ? pw1 : vw1;
        int o = (oc < 8) ? oc : oc - 8;
        float W0 = src[(o*54 + c0)*27 + tap];
        float W1 = src[(o*54 + c1)*27 + tap];
        float W2 = src[(o*54 + c2)*27 + tap];
        float v = (pack == 0) ? (W0 + W1 + W2) : ((pack == 1) ? (W0 + W1) : (W1 + W2));
        g_wc1[i] = v;
    }
    if (i < 27*8*16) {
        int oc = i & 15; int icg = (i >> 4) % 8; int t = (i >> 4) / 8;
        g_wp2[i] = (oc < 8) ? pw2[(oc*8 + icg)*27 + t] : vw2[((oc-8)*8 + icg)*27 + t];
    }
}

// ---------------- encoder as smem-tiled GEMM: 64-pos x 64-oc tile, 4x4 register blocks ----------------
__global__ __launch_bounds__(256) void enc_kernel(const float* __restrict__ src, const float* __restrict__ mul,
                                                  const float* __restrict__ w, const float* __restrict__ b, int variant) {
    __shared__ __align__(16) float ws[64*68];
    __shared__ __align__(16) float xs[64*68];
    __shared__ float bs[64];
    int tid = threadIdx.x;
    for (int i = tid; i < 4096; i += 256) ws[(i >> 6)*68 + (i & 63)] = w[i];
    if (tid < 64) bs[tid] = b[tid];

    int n  = blockIdx.x / ENC_BPN;
    int p0 = (blockIdx.x % ENC_BPN) * 64;

    {
        int pl = tid >> 2;
        int p = p0 + pl;
        int kc = (tid & 3) << 4;
        float vals[16];
        if (p < H3) {
            int z = p % HH, y = (p / HH) % HH, x = p / H2;
            int base0 = ((2*x)*S + (2*y))*S + (2*z);
            float m[8];
#pragma unroll
            for (int t = 0; t < 8; t++) {
                int dx = t >> 2, dy = (t >> 1) & 1, dz = t & 1;
                m[t] = mul[base0 + (dx*S + dy)*S + dz];
            }
#pragma unroll
            for (int q = 0; q < 16; q++) {
                int k = kc + q; int ic = k >> 3; int t = k & 7;
                int dx = t >> 2, dy = (t >> 1) & 1, dz = t & 1;
                vals[q] = src[(n*8 + ic)*S3 + base0 + (dx*S + dy)*S + dz] * m[t];
            }
        } else {
#pragma unroll
            for (int q = 0; q < 16; q++) vals[q] = 0.f;
        }
#pragma unroll
        for (int q = 0; q < 16; q++) xs[pl*68 + kc + q] = vals[q];
    }
    __syncthreads();

    int pg = tid & 15, og = tid >> 4;
    int ocb = og * 4;
    unsigned long long acc[4][4];
#pragma unroll
    for (int r = 0; r < 4; r++)
#pragma unroll
        for (int c = 0; c < 4; c++) acc[r][c] = 0ULL;

    for (int kk = 0; kk < 64; kk += 4) {
        ulonglong2 xv[4], wv[4];
#pragma unroll
        for (int r = 0; r < 4; r++)
            xv[r] = *reinterpret_cast<const ulonglong2*>(&xs[(pg + 16*r)*68 + kk]);
#pragma unroll
        for (int c = 0; c < 4; c++)
            wv[c] = *reinterpret_cast<const ulonglong2*>(&ws[(ocb + c)*68 + kk]);
#pragma unroll
        for (int r = 0; r < 4; r++)
#pragma unroll
            for (int c = 0; c < 4; c++) {
                fma2(acc[r][c], xv[r].x, wv[c].x);
                fma2(acc[r][c], xv[r].y, wv[c].y);
            }
    }

    float* outp = &g_f[variant][(n*64)*H3];
#pragma unroll
    for (int r = 0; r < 4; r++) {
        int p = p0 + pg + 16*r;
        if (p >= H3) continue;
#pragma unroll
        for (int c = 0; c < 4; c++) {
            float lo, hi;
            upk2(acc[r][c], lo, hi);
            outp[(ocb + c)*H3 + p] = bs[ocb + c] + lo + hi;
        }
    }
}

// ---------------- correlation: 18 distinct channels, s-pair f32x2 ----------------
__global__ void corr_kernel() {
    int idx = blockIdx.x * blockDim.x + threadIdx.x;
    if (idx >= NB*H3) return;
    int p = idx % H3; int n = idx / H3;
    int y = (p / HH) % HH, x = p / H2;

    const float* A0 = &g_f[0][n*64*H3 + p];
    const float* A1 = &g_f[1][n*64*H3 + p];
    const float* B  = &g_f[2][n*64*H3 + p];

    int off[9]; bool ok[9];
    {
        int s = 0;
        for (int di = -1; di <= 1; di++)
            for (int dj = -1; dj <= 1; dj++) {
                ok[s] = (x+di >= 0 && x+di < HH && y+dj >= 0 && y+dj < HH);
                off[s] = (di*HH + dj)*HH;
                s++;
            }
    }
    unsigned long long acc2[9];
#pragma unroll
    for (int s = 0; s < 9; s++) acc2[s] = 0ULL;

    for (int c = 0; c < 64; c++) {
        unsigned long long a2 = pk2(A0[c*H3], A1[c*H3]);
        const float* Bc = B + c*H3;
#pragma unroll
        for (int s = 0; s < 9; s++) {
            float bv = ok[s] ? Bc[off[s]] : 0.f;
            fma2(acc2[s], pk2(bv, bv), a2);
        }
    }
#pragma unroll
    for (int s = 0; s < 9; s++) {
        float a, bqq;
        upk2(acc2[s], a, bqq);
        g_corr[(n*18 + s    )*H3 + p] = a   * (1.f/64.f);
        g_corr[(n*18 + 9 + s)*H3 + p] = bqq * (1.f/64.f);
    }
}

// ---------------- conv1: 18 -> 16, 3^3, z-vectorized x3, f32x2, fused BN stat partials ----------------
__global__ void conv1_kernel() {
    extern __shared__ float ws[];
    __shared__ double sW[8][16][2];
    for (int i = threadIdx.x; i < 3*WC1_PACK; i += blockDim.x) ws[i] = g_wc1[i];
    __syncthreads();

    int idx = blockIdx.x * blockDim.x + threadIdx.x;
    bool valid = (idx < NB*H2*11);
    int zt = 0, y = 0, x = 0, n = 0;
    if (valid) {
        zt = idx % 11;
        y  = (idx / 11) % HH;
        x  = (idx / (11*HH)) % HH;
        n  = idx / (11*H2);
    }
    int z0 = 3*zt;

    unsigned long long acc2[3][8];
#pragma unroll
    for (int pp = 0; pp < 3; pp++)
#pragma unroll
        for (int i = 0; i < 8; i++) acc2[pp][i] = 0ULL;

    if (valid) {
        const float* cbase = g_corr + n*18*H3;
        bool interior = (zt >= 1 && zt <= 9);   // all window zz in [1,31]: pack0, no bounds

        for (int dx = -1; dx <= 1; dx++) {
            int xx = x + dx;
            if ((unsigned)xx >= (unsigned)HH) continue;
            for (int dy = -1; dy <= 1; dy++) {
                int yy = y + dy;
                if ((unsigned)yy >= (unsigned)HH) continue;
                int tap0 = ((dx+1)*3 + (dy+1))*3;
                int base = (xx*HH + yy)*HH + z0;

                if (interior) {
#pragma unroll 2
                    for (int ic = 0; ic < 18; ic++) {
                        const float* cp = cbase + ic*H3 + base;
                        unsigned long long vp[5];
#pragma unroll
                        for (int wq = 0; wq < 5; wq++) {
                            float f = cp[wq - 1];
                            vp[wq] = pk2(f, f);
                        }
#pragma unroll
                        for (int dz = 0; dz < 3; dz++) {
                            const ulonglong2* wp =
                                reinterpret_cast<const ulonglong2*>(ws + (tap0+dz)*288 + (ic << 4));
                            ulonglong2 w01 = wp[0], w23 = wp[1], w45 = wp[2], w67 = wp[3];
#pragma unroll
                            for (int pp = 0; pp < 3; pp++) {
                                unsigned long long v = vp[pp+dz];
                                fma2(acc2[pp][0], v, w01.x); fma2(acc2[pp][1], v, w01.y);
                                fma2(acc2[pp][2], v, w23.x); fma2(acc2[pp][3], v, w23.y);
                                fma2(acc2[pp][4], v, w45.x); fma2(acc2[pp][5], v, w45.y);
                                fma2(acc2[pp][6], v, w67.x); fma2(acc2[pp][7], v, w67.y);
                            }
                        }
                    }
                } else {
                    int sel[5];
                    bool okw[5];
#pragma unroll
                    for (int wq = 0; wq < 5; wq++) {
                        int zz = z0 - 1 + wq;
                        okw[wq] = ((unsigned)zz < (unsigned)HH);
                        sel[wq] = (zz == 0) ? 1 : ((zz == HH-1) ? 2 : 0);
                    }
                    for (int ic = 0; ic < 18; ic++) {
                        const float* cp = cbase + ic*H3 + base;
                        unsigned long long vp[5];
#pragma unroll
                        for (int wq = 0; wq < 5; wq++) {
                            float f = okw[wq] ? cp[wq - 1] : 0.f;
                            vp[wq] = pk2(f, f);
                        }
#pragma unroll
                        for (int dz = 0; dz < 3; dz++) {
#pragma unroll
                            for (int pp = 0; pp < 3; pp++) {
                                int wq = pp + dz;
                                const ulonglong2* wp = reinterpret_cast<const ulonglong2*>(
                                    ws + sel[wq]*WC1_PACK + (tap0+dz)*288 + (ic << 4));
                                ulonglong2 w01 = wp[0], w23 = wp[1], w45 = wp[2], w67 = wp[3];
                                unsigned long long v = vp[wq];
                                fma2(acc2[pp][0], v, w01.x); fma2(acc2[pp][1], v, w01.y);
                                fma2(acc2[pp][2], v, w23.x); fma2(acc2[pp][3], v, w23.y);
                                fma2(acc2[pp][4], v, w45.x); fma2(acc2[pp][5], v, w45.y);
                                fma2(acc2[pp][6], v, w67.x); fma2(acc2[pp][7], v, w67.y);
                            }
                        }
                    }
                }
            }
        }
    }

    int p0 = (x*HH + y)*HH + z0;
    int warp = threadIdx.x >> 5;
#pragma unroll
    for (int j = 0; j < 8; j++) {
        float sLo = 0.f, s2Lo = 0.f, sHi = 0.f, s2Hi = 0.f;
#pragma unroll
        for (int pp = 0; pp < 3; pp++) {
            float lo, hi;
            upk2(acc2[pp][j], lo, hi);
            if (valid) {
                g_c1[(n*16 + 2*j    )*H3 + p0 + pp] = lo;
                g_c1[(n*16 + 2*j + 1)*H3 + p0 + pp] = hi;
                sLo += lo; s2Lo += lo*lo;
                sHi += hi; s2Hi += hi*hi;
            }
        }
        float a = wred(sLo), b = wred(s2Lo);
        float c = wred(sHi), d = wred(s2Hi);
        if ((threadIdx.x & 31) == 0) {
            sW[warp][2*j  ][0] = (double)a; sW[warp][2*j  ][1] = (double)b;
            sW[warp][2*j+1][0] = (double)c; sW[warp][2*j+1][1] = (double)d;
        }
        __syncwarp();
    }
    __syncthreads();
    if (threadIdx.x < 16) {
        double s = 0.0, s2 = 0.0;
        for (int wi = 0; wi < 8; wi++) { s += sW[wi][threadIdx.x][0]; s2 += sW[wi][threadIdx.x][1]; }
        g_pc1[(threadIdx.x*NBLK1 + blockIdx.x)*2 + 0] = s;
        g_pc1[(threadIdx.x*NBLK1 + blockIdx.x)*2 + 1] = s2;
    }
}

// ---------------- stats reduce: per-channel partial sums -> mean/istd ----------------
__global__ void stats_reduce(int phase) {
    int ch = blockIdx.x;
    int NP = phase ? NBLK2 : NBLK1;
    const double* src = phase ? g_pc2 : g_pc1;
    __shared__ double sh[256], sh2[256];
    double s = 0.0, s2 = 0.0;
    for (int i = threadIdx.x; i < NP; i += 256) {
        s  += src[(ch*NP + i)*2 + 0];
        s2 += src[(ch*NP + i)*2 + 1];
    }
    sh[threadIdx.x] = s; sh2[threadIdx.x] = s2;
    __syncthreads();
    for (int st = 128; st > 0; st >>= 1) {
        if (threadIdx.x < st) { sh[threadIdx.x] += sh[threadIdx.x+st]; sh2[threadIdx.x] += sh2[threadIdx.x+st]; }
        __syncthreads();
    }
    if (threadIdx.x == 0) {
        double total = (double)NB * (phase ? S3 : H3);
        double mean = sh[0] / total;
        double var  = sh2[0] / total - mean*mean;
        g_stat[phase*32 + ch]      = (float)mean;
        g_stat[phase*32 + 16 + ch] = (float)(1.0 / sqrt(var + 1e-5));
    }
}

// ---------------- BN1 + relu + trilinear upsample x2 (align_corners) ----------------
__device__ __forceinline__ float bnrelu(float v, float sc, float sh) { return fmaxf(v*sc + sh, 0.f); }

__global__ void upsample_kernel(const float* __restrict__ g1p, const float* __restrict__ b1p,
                                const float* __restrict__ g1v, const float* __restrict__ b1v) {
    int idx = blockIdx.x * blockDim.x + threadIdx.x;
    if (idx >= NB*16*S3) return;
    int p = idx % S3; int ch = (idx / S3) % 16; int n = idx / (16*S3);
    int Z = p % S, Y = (p / S) % S, X = p / S2;

    float mean = g_stat[ch], istd = g_stat[16 + ch];
    float gg = (ch < 8) ? g1p[ch] : g1v[ch-8];
    float bb = (ch < 8) ? b1p[ch] : b1v[ch-8];
    float sc = istd * gg, sh = bb - mean * sc;

    const float SC = 32.f / 65.f;
    float sx = X * SC; int x0 = (int)sx; float fx = sx - x0; int x1 = min(x0+1, 32);
    float sy = Y * SC; int y0 = (int)sy; float fy = sy - y0; int y1 = min(y0+1, 32);
    float sz = Z * SC; int z0 = (int)sz; float fz = sz - z0; int z1 = min(z0+1, 32);

    const float* base = g_c1 + (n*16 + ch)*H3;
#define RD(xi,yi,zi) bnrelu(base[((xi)*HH+(yi))*HH+(zi)], sc, sh)
    float v =
      ((RD(x0,y0,z0)*(1-fx) + RD(x1,y0,z0)*fx)*(1-fy) + (RD(x0,y1,z0)*(1-fx) + RD(x1,y1,z0)*fx)*fy)*(1-fz)
    + ((RD(x0,y0,z1)*(1-fx) + RD(x1,y0,z1)*fx)*(1-fy) + (RD(x0,y1,z1)*(1-fx) + RD(x1,y1,z1)*fx)*fy)*fz;
#undef RD
    g_u1[idx] = v;
}

// ---------------- conv2: grouped 2x(8->8), z-vec x3, f32x2, fused BN stat partials ----------------
__global__ void conv2_kernel() {
    __shared__ __align__(16) float ws[27*8*16];
    __shared__ double sW[8][16][2];
    for (int i = threadIdx.x; i < 27*8*16; i += blockDim.x) ws[i] = g_wp2[i];
    __syncthreads();

    int idx = blockIdx.x * blockDim.x + threadIdx.x;
    bool valid = (idx < NB*S*S*22);
    int zt = 0, y = 0, x = 0, n = 0;
    if (valid) {
        zt = idx % 22;
        y  = (idx / 22) % S;
        x  = (idx / (22*S)) % S;
        n  = idx / (22*S*S);
    }
    int z0 = 3*zt;

    unsigned long long acc2[3][8];
#pragma unroll
    for (int pp = 0; pp < 3; pp++)
#pragma unroll
        for (int i = 0; i < 8; i++) acc2[pp][i] = 0ULL;

    if (valid) {
        const float* ubase = g_u1 + n*16*S3;
        bool zlo = (zt == 0);
        bool zhi = (zt == 21);

#pragma unroll
        for (int dx = -1; dx <= 1; dx++) {
            int xx = x + dx;
            if ((unsigned)xx >= (unsigned)S) continue;
#pragma unroll
            for (int dy = -1; dy <= 1; dy++) {
                int yy = y + dy;
                if ((unsigned)yy >= (unsigned)S) continue;
                int tap0 = ((dx+1)*3 + (dy+1))*3;
                const float* col = ubase + (xx*S + yy)*S + z0;
#pragma unroll
                for (int icg = 0; icg < 8; icg++) {
                    const float* cp = col + icg*S3;
                    const float* cv = col + (8+icg)*S3;
                    float inp[5], inv[5];
                    inp[0] = zlo ? 0.f : cp[-1];  inv[0] = zlo ? 0.f : cv[-1];
                    inp[1] = cp[0];               inv[1] = cv[0];
                    inp[2] = cp[1];               inv[2] = cv[1];
                    inp[3] = cp[2];               inv[3] = cv[2];
                    inp[4] = zhi ? 0.f : cp[3];   inv[4] = zhi ? 0.f : cv[3];
                    unsigned long long ip2[5], iv2[5];
#pragma unroll
                    for (int t = 0; t < 5; t++) { ip2[t] = pk2(inp[t], inp[t]); iv2[t] = pk2(inv[t], inv[t]); }
#pragma unroll
                    for (int dz = 0; dz < 3; dz++) {
                        const ulonglong2* wp =
                            reinterpret_cast<const ulonglong2*>(ws + (((tap0+dz)*8 + icg) << 4));
                        ulonglong2 w01 = wp[0], w23 = wp[1], w45 = wp[2], w67 = wp[3];
#pragma unroll
                        for (int pp = 0; pp < 3; pp++) {
                            unsigned long long vp = ip2[pp+dz];
                            unsigned long long vv = iv2[pp+dz];
                            fma2(acc2[pp][0], vp, w01.x); fma2(acc2[pp][1], vp, w01.y);
                            fma2(acc2[pp][2], vp, w23.x); fma2(acc2[pp][3], vp, w23.y);
                            fma2(acc2[pp][4], vv, w45.x); fma2(acc2[pp][5], vv, w45.y);
                            fma2(acc2[pp][6], vv, w67.x); fma2(acc2[pp][7], vv, w67.y);
                        }
                    }
                }
            }
        }
    }

    int ob = (x*S + y)*S + z0;
    int warp = threadIdx.x >> 5;
#pragma unroll
    for (int j = 0; j < 8; j++) {
        float sLo = 0.f, s2Lo = 0.f, sHi = 0.f, s2Hi = 0.f;
#pragma unroll
        for (int pp = 0; pp < 3; pp++) {
            float lo, hi;
            upk2(acc2[pp][j], lo, hi);
            if (valid) {
                g_c2[(n*16 + 2*j    )*S3 + ob + pp] = lo;
                g_c2[(n*16 + 2*j + 1)*S3 + ob + pp] = hi;
                sLo += lo; s2Lo += lo*lo;
                sHi += hi; s2Hi += hi*hi;
            }
        }
        float a = wred(sLo), b = wred(s2Lo);
        float c = wred(sHi), d = wred(s2Hi);
        if ((threadIdx.x & 31) == 0) {
            sW[warp][2*j  ][0] = (double)a; sW[warp][2*j  ][1] = (double)b;
            sW[warp][2*j+1][0] = (double)c; sW[warp][2*j+1][1] = (double)d;
        }
        __syncwarp();
    }
    __syncthreads();
    if (threadIdx.x < 16) {
        double s = 0.0, s2 = 0.0;
        for (int wi = 0; wi < 8; wi++) { s += sW[wi][threadIdx.x][0]; s2 += sW[wi][threadIdx.x][1]; }
        g_pc2[(threadIdx.x*NBLK2 + blockIdx.x)*2 + 0] = s;
        g_pc2[(threadIdx.x*NBLK2 + blockIdx.x)*2 + 1] = s2;
    }
}

// ---------------- BN2 + relu + 1x1 heads -> helmholtz (into d_out) ----------------
__global__ void helm_kernel(const float* __restrict__ g2p, const float* __restrict__ b2p,
                            const float* __restrict__ g2v, const float* __restrict__ b2v,
                            const float* __restrict__ pow_, const float* __restrict__ pob,
                            const float* __restrict__ vow,  const float* __restrict__ vob,
                            const float* __restrict__ phiw, const float* __restrict__ vortw,
                            float* __restrict__ out) {
    int idx = blockIdx.x * blockDim.x + threadIdx.x;
    if (idx >= NB*S3) return;
    int p = idx % S3; int n = idx / S3;

    float y[16];
#pragma unroll
    for (int c = 0; c < 16; c++) {
        float mean = g_stat[32 + c], istd = g_stat[48 + c];
        float gg = (c < 8) ? g2p[c] : g2v[c-8];
        float bb = (c < 8) ? b2p[c] : b2v[c-8];
        float v = (g_c2[(n*16 + c)*S3 + p] - mean) * istd * gg + bb;
        y[c] = fmaxf(v, 0.f);
    }
    float ph = pob[0];
#pragma unroll
    for (int c = 0; c < 8; c++) ph += y[c] * pow_[c];
    ph *= phiw[0];
    out[OFF_HELM + (n*4)*S3 + p] = ph;
    float vscale = vortw[0] * 66.f;
#pragma unroll
    for (int r = 0; r < 3; r++) {
        float v = vob[r];
#pragma unroll
        for (int c = 0; c < 8; c++) v += y[8+c] * vow[r*8 + c];
        out[OFF_HELM + (n*4 + 1 + r)*S3 + p] = v * vscale;
    }
}

// ---------------- velocity stencils (into d_out) ----------------
__device__ __forceinline__ float HV(const float* hm, int ch, int x, int y, int z) {
    return hm[ch*S3 + (x*S + y)*S + z];
}

__global__ void vel_kernel(float* __restrict__ out) {
    int idx = blockIdx.x * blockDim.x + threadIdx.x;
    if (idx >= NB*D3) return;
    int p = idx % D3; int n = idx / D3;
    int k = p & 63, j = (p >> 6) & 63, i = p >> 12;
    const float* hm = out + OFF_HELM + n*4*S3;

    float vp0 = 0.5f * (HV(hm,0, 1+i, 1+j, k+2) - HV(hm,0, 1+i, 1+j, k));
    float vp1 = 0.5f * (HV(hm,0, 1+i, j+2, 1+k) - HV(hm,0, 1+i, j,   1+k));
    float vp2 = 0.5f * (HV(hm,0, i+2, 1+j, 1+k) - HV(hm,0, i,   1+j, 1+k));

    float ua = (HV(hm,2, 2+i,1+j,k+1) - HV(hm,2, 1+i,1+j,k+1)) - (HV(hm,1, 1+i,2+j,k+1) - HV(hm,1, 1+i,1+j,k+1));
    float ub = (HV(hm,2, 2+i,1+j,k  ) - HV(hm,2, 1+i,1+j,k  )) - (HV(hm,1, 1+i,2+j,k  ) - HV(hm,1, 1+i,1+j,k  ));
    float vv0 = 0.5f * (ua + ub);
    float va = (HV(hm,1, 1+i,j+1,k+2) - HV(hm,1, 1+i,j+1,k+1)) - (HV(hm,3, i+2,j+1,k+1) - HV(hm,3, i+1,j+1,k+1));
    float vb = (HV(hm,1, 1+i,j,  k+2) - HV(hm,1, 1+i,j,  k+1)) - (HV(hm,3, i+2,j,  k+1) - HV(hm,3, i+1,j,  k+1));
    float vv1 = 0.5f * (va + vb);
    float wa = (HV(hm,3, i+1,j+2,k+1) - HV(hm,3, i+1,j+1,k+1)) - (HV(hm,2, i+1,j+1,k+2) - HV(hm,2, i+1,j+1,k+1));
    float wb = (HV(hm,3, i,  j+2,k+1) - HV(hm,3, i,  j+1,k+1)) - (HV(hm,2, i,  j+1,k+2) - HV(hm,2, i,  j+1,k+1));
    float vv2 = 0.5f * (wa + wb);

    int b = n*3*D3 + p;
    out[OFF_VPHI  + b        ] = vp0;
    out[OFF_VPHI  + b + D3   ] = vp1;
    out[OFF_VPHI  + b + 2*D3 ] = vp2;
    out[OFF_VVORT + b        ] = vv0;
    out[OFF_VVORT + b + D3   ] = vv1;
    out[OFF_VVORT + b + 2*D3 ] = vv2;
    out[OFF_VEL   + b        ] = vp0 + vv0;
    out[OFF_VEL   + b + D3   ] = vp1 + vv1;
    out[OFF_VEL   + b + 2*D3 ] = vp2 + vv2;
}

// ---------------- BFECC advect passes ----------------
__global__ void advect_kernel(const float* __restrict__ ext_src, const float* __restrict__ tex,
                              const float* __restrict__ vel, float sgn, int mode) {
    int idx = blockIdx.x * blockDim.x + threadIdx.x;
    if (idx >= NB*D3) return;
    int p = idx % D3; int n = idx / D3;
    int k = p & 63, j = (p >> 6) & 63, i = p >> 12;

    float v0 = vel[(n*3    )*D3 + p];
    float v1 = vel[(n*3 + 1)*D3 + p];
    float v2 = vel[(n*3 + 2)*D3 + p];
    float px = (float)i - sgn*v2;
    float py = (float)j - sgn*v1;
    float pz = (float)k - sgn*v0;
    px = fminf(fmaxf(px, 0.f), 63.f);
    py = fminf(fmaxf(py, 0.f), 63.f);
    pz = fminf(fmaxf(pz, 0.f), 63.f);
    int x0 = (int)px; float fx = px - x0; int x1 = min(x0+1, 63);
    int y0 = (int)py; float fy = py - y0; int y1 = min(y0+1, 63);
    int z0 = (int)pz; float fz = pz - z0; int z1 = min(z0+1, 63);

    float w000 = (1-fx)*(1-fy)*(1-fz), w001 = (1-fx)*(1-fy)*fz;
    float w010 = (1-fx)*fy*(1-fz),     w011 = (1-fx)*fy*fz;
    float w100 = fx*(1-fy)*(1-fz),     w101 = fx*(1-fy)*fz;
    float w110 = fx*fy*(1-fz),         w111 = fx*fy*fz;

    int b00 = (x0*64 + y0)*64, b01 = (x0*64 + y1)*64;
    int b10 = (x1*64 + y0)*64, b11 = (x1*64 + y1)*64;

    const float* src = (mode == 0) ? ext_src : ((mode == 1) ? g_phi1 : g_comb);
    float* dst = (mode == 0) ? g_phi1 : ((mode == 1) ? g_comb : g_pred);

#pragma unroll
    for (int c = 0; c < 8; c++) {
        const float* s = src + (n*8 + c)*D3;
        float v = w000*s[b00+z0] + w001*s[b00+z1] + w010*s[b01+z0] + w011*s[b01+z1]
                + w100*s[b10+z0] + w101*s[b10+z1] + w110*s[b11+z0] + w111*s[b11+z1];
        if (mode == 1) v = 1.5f * tex[(n*8 + c)*D3 + p] - 0.5f * v;
        dst[(n*8 + c)*D3 + p] = v;
    }
}

// ---------------- fused LN + FF (LN, @W1+b1, GELU, @W2+b2, residual -> d_out) ----------------
__global__ void ff_kernel(const float* __restrict__ lng, const float* __restrict__ lnb,
                          const float* __restrict__ w1, const float* __restrict__ b1,
                          const float* __restrict__ w2, const float* __restrict__ b2,
                          float* __restrict__ out) {
    __shared__ __align__(16) unsigned long long Wp1[2048];
    __shared__ __align__(16) unsigned long long Wp2[2048];
    __shared__ float Bv1[64], Bv2[64], G[64], Bt[64];
    float* fW1 = reinterpret_cast<float*>(Wp1);
    float* fW2 = reinterpret_cast<float*>(Wp2);
    for (int i = threadIdx.x; i < 4096; i += blockDim.x) {
        int ii = i >> 6, jj = i & 63;
        int d = (jj*32 + (ii >> 1))*2 + (ii & 1);
        fW1[d] = w1[i];
        fW2[d] = w2[i];
    }
    if (threadIdx.x < 64) {
        Bv1[threadIdx.x] = b1[threadIdx.x]; Bv2[threadIdx.x] = b2[threadIdx.x];
        G[threadIdx.x] = lng[threadIdx.x];  Bt[threadIdx.x] = lnb[threadIdx.x];
    }
    __syncthreads();

    int p = blockIdx.x * blockDim.x + threadIdx.x;
    if (p >= D3) return;

    float h[64]; float s = 0.f, s2 = 0.f;
#pragma unroll
    for (int c = 0; c < 64; c++) { float v = g_pred[c*D3 + p]; h[c] = v; s += v; s2 += v*v; }
    float mean = s * (1.f/64.f);
    float var  = s2 * (1.f/64.f) - mean*mean;
    float is = rsqrtf(var + 1e-5f);
    unsigned long long hp[32];
#pragma unroll
    for (int c = 0; c < 32; c++) {
        float e = (h[2*c]   - mean) * is * G[2*c]   + Bt[2*c];
        float o = (h[2*c+1] - mean) * is * G[2*c+1] + Bt[2*c+1];
        hp[c] = pk2(e, o);
    }

    unsigned long long gp[32];
    for (int jj = 0; jj < 64; jj += 2) {
        const ulonglong2* wrA = reinterpret_cast<const ulonglong2*>(Wp1 + jj*32);
        const ulonglong2* wrB = reinterpret_cast<const ulonglong2*>(Wp1 + (jj+1)*32);
        unsigned long long a0 = 0ULL, a1 = 0ULL, c0 = 0ULL, c1 = 0ULL;
#pragma unroll
        for (int q = 0; q < 16; q++) {
            ulonglong2 wa = wrA[q];
            ulonglong2 wb = wrB[q];
            fma2(a0, hp[2*q],   wa.x);
            fma2(a1, hp[2*q+1], wa.y);
            fma2(c0, hp[2*q],   wb.x);
            fma2(c1, hp[2*q+1], wb.y);
        }
        float l0, h0, l1, h1;
        upk2(a0, l0, h0); upk2(a1, l1, h1);
        float aA = Bv1[jj] + ((l0 + h0) + (l1 + h1));
        upk2(c0, l0, h0); upk2(c1, l1, h1);
        float aB = Bv1[jj+1] + ((l0 + h0) + (l1 + h1));
        float gA = 0.5f * aA * (1.f + erff(aA * 0.70710678118f));
        float gB = 0.5f * aB * (1.f + erff(aB * 0.70710678118f));
        gp[jj >> 1] = pk2(gA, gB);
    }

    for (int jj = 0; jj < 64; jj++) {
        const ulonglong2* wr = reinterpret_cast<const ulonglong2*>(Wp2 + jj*32);
        unsigned long long a0 = 0ULL, a1 = 0ULL;
#pragma unroll
        for (int q = 0; q < 16; q++) {
            ulonglong2 w2v = wr[q];
            fma2(a0, gp[2*q],   w2v.x);
            fma2(a1, gp[2*q+1], w2v.y);
        }
        float l0, h0, l1, h1;
        upk2(a0, l0, h0); upk2(a1, l1, h1);
        float a = Bv2[jj] + ((l0 + h0) + (l1 + h1));
        out[OFF_X + jj*D3 + p] = h[jj] + a;     // residual from registers
    }
}

// ---------------- host launch ----------------
extern "C" void kernel_launch(void* const* d_in, const int* in_sizes, int n_in,
                              void* d_out, int out_size) {
    const float* prev      = (const float*)d_in[0];
    const float* nxt       = (const float*)d_in[1];
    const float* texture   = (const float*)d_in[2];
    const float* mask      = (const float*)d_in[3];
    const float* boundary  = (const float*)d_in[4];
    const float* enc_w     = (const float*)d_in[5];
    const float* enc_b     = (const float*)d_in[6];
    const float* phi_c1_w  = (const float*)d_in[7];
    const float* phi_bn1_g = (const float*)d_in[8];
    const float* phi_bn1_b = (const float*)d_in[9];
    const float* phi_c2_w  = (const float*)d_in[10];
    const float* phi_bn2_g = (const float*)d_in[11];
    const float* phi_bn2_b = (const float*)d_in[12];
    const float* phi_out_w = (const float*)d_in[13];
    const float* phi_out_b = (const float*)d_in[14];
    const float* vort_c1_w = (const float*)d_in[15];
    const float* vort_bn1_g= (const float*)d_in[16];
    const float* vort_bn1_b= (const float*)d_in[17];
    const float* vort_c2_w = (const float*)d_in[18];
    const float* vort_bn2_g= (const float*)d_in[19];
    const float* vort_bn2_b= (const float*)d_in[20];
    const float* vort_out_w= (const float*)d_in[21];
    const float* vort_out_b= (const float*)d_in[22];
    const float* phi_weight= (const float*)d_in[23];
    const float* vort_weight=(const float*)d_in[24];
    const float* ln_g      = (const float*)d_in[25];
    const float* ln_b      = (const float*)d_in[26];
    const float* ff_w1     = (const float*)d_in[27];
    const float* ff_b1     = (const float*)d_in[28];
    const float* ff_w2     = (const float*)d_in[29];
    const float* ff_b2     = (const float*)d_in[30];
    float* out = (float*)d_out;

    pack_kernel<<<(3*WC1_PACK + 255)/256, 256>>>(phi_c1_w, vort_c1_w, phi_c2_w, vort_c2_w);

    int encBlocks = NB * ENC_BPN;
    enc_kernel<<<encBlocks, 256>>>(prev, mask,     enc_w, enc_b, 0);
    enc_kernel<<<encBlocks, 256>>>(prev, boundary, enc_w, enc_b, 1);
    enc_kernel<<<encBlocks, 256>>>(nxt,  mask,     enc_w, enc_b, 2);

    corr_kernel<<<(NB*H3 + 255)/256, 256>>>();

    cudaFuncSetAttribute(conv1_kernel, cudaFuncAttributeMaxDynamicSharedMemorySize, 3*WC1_PACK*4);
    conv1_kernel<<<NBLK1, 256, 3*WC1_PACK*4>>>();
    stats_reduce<<<16, 256>>>(0);

    int upN = NB*16*S3;
    upsample_kernel<<<(upN + 255)/256, 256>>>(phi_bn1_g, phi_bn1_b, vort_bn1_g, vort_bn1_b);

    conv2_kernel<<<NBLK2, 256>>>();
    stats_reduce<<<16, 256>>>(1);

    helm_kernel<<<(NB*S3 + 255)/256, 256>>>(phi_bn2_g, phi_bn2_b, vort_bn2_g, vort_bn2_b,
                                            phi_out_w, phi_out_b, vort_out_w, vort_out_b,
                                            phi_weight, vort_weight, out);

    vel_kernel<<<(NB*D3 + 255)/256, 256>>>(out);

    const float* vel = out + OFF_VEL;
    advect_kernel<<<(NB*D3 + 255)/256, 256>>>(texture, texture, vel,  1.f, 0);
    advect_kernel<<<(NB*D3 + 255)/256, 256>>>(texture, texture, vel, -1.f, 1);
    advect_kernel<<<(NB*D3 + 255)/256, 256>>>(texture, texture, vel,  1.f, 2);

    ff_kernel<<<(D3 + 127)/128, 128>>>(ln_g, ln_b, ff_w1, ff_b1, ff_w2, ff_b2, out);
}

// round 17
// speedup vs baseline: 1.0041x; 1.0041x over previous
#include <cuda_runtime.h>
#include <math.h>

// ---------------- dimensions ----------------
#define NB 8          // batch*groups
#define S  66
#define S2 4356       // 66*66
#define S3 287496     // 66^3
#define HH 33
#define H2 1089       // 33*33
#define H3 35937      // 33^3
#define D3 262144     // 64^3

// output packing offsets (x, helmholtz, vel, vel_phi, vel_vort)
#define OFF_X     0
#define OFF_HELM  16777216
#define OFF_VEL   25977088
#define OFF_VPHI  32268544
#define OFF_VVORT 38560000

#define WC1_PACK 7776          // 18*27*16
#define NBLK1 375              // conv1 blocks: ceil(NB*33*33*11/256)
#define NBLK2 2995             // conv2 blocks: ceil(NB*66*66*22/256)
#define ENC_BPN 562            // ceil(H3/64)

// ---------------- scratch (static device memory; no allocation APIs) ----------------
__device__ float g_f[3][NB*64*H3];     // encoder outputs: pm, pb, nm
__device__ float g_corr[NB*18*H3];     // correlation output (18 distinct channels)
__device__ float g_c1[NB*16*H3];       // conv1 raw out (phi 0-7, vort 8-15)
__device__ float g_u1[NB*16*S3];       // upsampled (post BN1+relu)
__device__ float g_c2[NB*16*S3];       // conv2 raw out
__device__ float g_phi1[64*D3];        // advect pass 1
__device__ float g_comb[64*D3];        // 1.5*tex - 0.5*phi2
__device__ float g_pred[64*D3];        // final advect result
__device__ float g_wc1[3*WC1_PACK];    // conv1 summed packs
__device__ float g_wp2[27*8*16];       // packed conv2 weights
__device__ float g_stat[64];           // mean1[16], istd1[16], mean2[16], istd2[16]
__device__ double g_pc1[16*NBLK1*2];   // conv1 per-block stat partials
__device__ double g_pc2[16*NBLK2*2];   // conv2 per-block stat partials

// ---------------- packed f32x2 helpers (sm_103a FFMA2 via PTX) ----------------
__device__ __forceinline__ unsigned long long pk2(float a, float b) {
    unsigned long long r;
    asm("mov.b64 %0, {%1, %2};" : "=l"(r) : "f"(a), "f"(b));
    return r;
}
__device__ __forceinline__ void fma2(unsigned long long& d, unsigned long long a, unsigned long long b) {
    asm("fma.rn.f32x2 %0, %1, %2, %0;" : "+l"(d) : "l"(a), "l"(b));
}
__device__ __forceinline__ void upk2(unsigned long long v, float& lo, float& hi) {
    asm("mov.b64 {%0, %1}, %2;" : "=f"(lo), "=f"(hi) : "l"(v));
}
__device__ __forceinline__ float wred(float v) {
#pragma unroll
    for (int o = 16; o > 0; o >>= 1) v += __shfl_down_sync(0xffffffffu, v, o);
    return v;
}

// ---------------- weight packing ----------------
__global__ void pack_kernel(const float* __restrict__ pw1, const float* __restrict__ vw1,
                            const float* __restrict__ pw2, const float* __restrict__ vw2) {
    int i = blockIdx.x * blockDim.x + threadIdx.x;
    if (i < 3*WC1_PACK) {
        int pack = i / WC1_PACK; int r = i % WC1_PACK;
        int oc = r & 15; int t18 = r >> 4; int ic = t18 % 18; int tap = t18 / 18;
        int w = ic / 9, s = ic % 9;
        int c0 = w*27 + s, c1 = c0 + 9, c2 = c0 + 18;
        const float* src = (oc < 8) ? pw1 : vw1;
        int o = (oc < 8) ? oc : oc - 8;
        float W0 = src[(o*54 + c0)*27 + tap];
        float W1 = src[(o*54 + c1)*27 + tap];
        float W2 = src[(o*54 + c2)*27 + tap];
        float v = (pack == 0) ? (W0 + W1 + W2) : ((pack == 1) ? (W0 + W1) : (W1 + W2));
        g_wc1[i] = v;
    }
    if (i < 27*8*16) {
        int oc = i & 15; int icg = (i >> 4) % 8; int t = (i >> 4) / 8;
        g_wp2[i] = (oc < 8) ? pw2[(oc*8 + icg)*27 + t] : vw2[((oc-8)*8 + icg)*27 + t];
    }
}

// ---------------- encoder as smem-tiled GEMM: 64-pos x 64-oc tile, 4x4 register blocks ----------------
__global__ __launch_bounds__(256) void enc_kernel(const float* __restrict__ src, const float* __restrict__ mul,
                                                  const float* __restrict__ w, const float* __restrict__ b, int variant) {
    __shared__ __align__(16) float ws[64*68];
    __shared__ __align__(16) float xs[64*68];
    __shared__ float bs[64];
    int tid = threadIdx.x;
    for (int i = tid; i < 4096; i += 256) ws[(i >> 6)*68 + (i & 63)] = w[i];
    if (tid < 64) bs[tid] = b[tid];

    int n  = blockIdx.x / ENC_BPN;
    int p0 = (blockIdx.x % ENC_BPN) * 64;

    {
        int pl = tid >> 2;
        int p = p0 + pl;
        int kc = (tid & 3) << 4;
        float vals[16];
        if (p < H3) {
            int z = p % HH, y = (p / HH) % HH, x = p / H2;
            int base0 = ((2*x)*S + (2*y))*S + (2*z);
            float m[8];
#pragma unroll
            for (int t = 0; t < 8; t++) {
                int dx = t >> 2, dy = (t >> 1) & 1, dz = t & 1;
                m[t] = mul[base0 + (dx*S + dy)*S + dz];
            }
#pragma unroll
            for (int q = 0; q < 16; q++) {
                int k = kc + q; int ic = k >> 3; int t = k & 7;
                int dx = t >> 2, dy = (t >> 1) & 1, dz = t & 1;
                vals[q] = src[(n*8 + ic)*S3 + base0 + (dx*S + dy)*S + dz] * m[t];
            }
        } else {
#pragma unroll
            for (int q = 0; q < 16; q++) vals[q] = 0.f;
        }
#pragma unroll
        for (int q = 0; q < 16; q++) xs[pl*68 + kc + q] = vals[q];
    }
    __syncthreads();

    int pg = tid & 15, og = tid >> 4;
    int ocb = og * 4;
    unsigned long long acc[4][4];
#pragma unroll
    for (int r = 0; r < 4; r++)
#pragma unroll
        for (int c = 0; c < 4; c++) acc[r][c] = 0ULL;

    for (int kk = 0; kk < 64; kk += 4) {
        ulonglong2 xv[4], wv[4];
#pragma unroll
        for (int r = 0; r < 4; r++)
            xv[r] = *reinterpret_cast<const ulonglong2*>(&xs[(pg + 16*r)*68 + kk]);
#pragma unroll
        for (int c = 0; c < 4; c++)
            wv[c] = *reinterpret_cast<const ulonglong2*>(&ws[(ocb + c)*68 + kk]);
#pragma unroll
        for (int r = 0; r < 4; r++)
#pragma unroll
            for (int c = 0; c < 4; c++) {
                fma2(acc[r][c], xv[r].x, wv[c].x);
                fma2(acc[r][c], xv[r].y, wv[c].y);
            }
    }

    float* outp = &g_f[variant][(n*64)*H3];
#pragma unroll
    for (int r = 0; r < 4; r++) {
        int p = p0 + pg + 16*r;
        if (p >= H3) continue;
#pragma unroll
        for (int c = 0; c < 4; c++) {
            float lo, hi;
            upk2(acc[r][c], lo, hi);
            outp[(ocb + c)*H3 + p] = bs[ocb + c] + lo + hi;
        }
    }
}

// ---------------- correlation: 18 distinct channels, s-pair f32x2 ----------------
__global__ void corr_kernel() {
    int idx = blockIdx.x * blockDim.x + threadIdx.x;
    if (idx >= NB*H3) return;
    int p = idx % H3; int n = idx / H3;
    int y = (p / HH) % HH, x = p / H2;

    const float* A0 = &g_f[0][n*64*H3 + p];
    const float* A1 = &g_f[1][n*64*H3 + p];
    const float* B  = &g_f[2][n*64*H3 + p];

    int off[9]; bool ok[9];
    {
        int s = 0;
        for (int di = -1; di <= 1; di++)
            for (int dj = -1; dj <= 1; dj++) {
                ok[s] = (x+di >= 0 && x+di < HH && y+dj >= 0 && y+dj < HH);
                off[s] = (di*HH + dj)*HH;
                s++;
            }
    }
    unsigned long long acc2[9];
#pragma unroll
    for (int s = 0; s < 9; s++) acc2[s] = 0ULL;

    for (int c = 0; c < 64; c++) {
        unsigned long long a2 = pk2(A0[c*H3], A1[c*H3]);
        const float* Bc = B + c*H3;
#pragma unroll
        for (int s = 0; s < 9; s++) {
            float bv = ok[s] ? Bc[off[s]] : 0.f;
            fma2(acc2[s], pk2(bv, bv), a2);
        }
    }
#pragma unroll
    for (int s = 0; s < 9; s++) {
        float a, bqq;
        upk2(acc2[s], a, bqq);
        g_corr[(n*18 + s    )*H3 + p] = a   * (1.f/64.f);
        g_corr[(n*18 + 9 + s)*H3 + p] = bqq * (1.f/64.f);
    }
}

// ---------------- conv1: 18 -> 16, 3^3, z-vectorized x3, f32x2, fused BN stat partials ----------------
__global__ void conv1_kernel() {
    extern __shared__ float ws[];
    __shared__ double sW[8][16][2];
    for (int i = threadIdx.x; i < 3*WC1_PACK; i += blockDim.x) ws[i] = g_wc1[i];
    __syncthreads();

    int idx = blockIdx.x * blockDim.x + threadIdx.x;
    bool valid = (idx < NB*H2*11);
    int zt = 0, y = 0, x = 0, n = 0;
    if (valid) {
        zt = idx % 11;
        y  = (idx / 11) % HH;
        x  = (idx / (11*HH)) % HH;
        n  = idx / (11*H2);
    }
    int z0 = 3*zt;

    unsigned long long acc2[3][8];
#pragma unroll
    for (int pp = 0; pp < 3; pp++)
#pragma unroll
        for (int i = 0; i < 8; i++) acc2[pp][i] = 0ULL;

    if (valid) {
        const float* cbase = g_corr + n*18*H3;
        bool interior = (zt >= 1 && zt <= 9);   // all window zz in [1,31]: pack0, no bounds

        for (int dx = -1; dx <= 1; dx++) {
            int xx = x + dx;
            if ((unsigned)xx >= (unsigned)HH) continue;
            for (int dy = -1; dy <= 1; dy++) {
                int yy = y + dy;
                if ((unsigned)yy >= (unsigned)HH) continue;
                int tap0 = ((dx+1)*3 + (dy+1))*3;
                int base = (xx*HH + yy)*HH + z0;

                if (interior) {
#pragma unroll 2
                    for (int ic = 0; ic < 18; ic++) {
                        const float* cp = cbase + ic*H3 + base;
                        unsigned long long vp[5];
#pragma unroll
                        for (int wq = 0; wq < 5; wq++) {
                            float f = cp[wq - 1];
                            vp[wq] = pk2(f, f);
                        }
#pragma unroll
                        for (int dz = 0; dz < 3; dz++) {
                            const ulonglong2* wp =
                                reinterpret_cast<const ulonglong2*>(ws + (tap0+dz)*288 + (ic << 4));
                            ulonglong2 w01 = wp[0], w23 = wp[1], w45 = wp[2], w67 = wp[3];
#pragma unroll
                            for (int pp = 0; pp < 3; pp++) {
                                unsigned long long v = vp[pp+dz];
                                fma2(acc2[pp][0], v, w01.x); fma2(acc2[pp][1], v, w01.y);
                                fma2(acc2[pp][2], v, w23.x); fma2(acc2[pp][3], v, w23.y);
                                fma2(acc2[pp][4], v, w45.x); fma2(acc2[pp][5], v, w45.y);
                                fma2(acc2[pp][6], v, w67.x); fma2(acc2[pp][7], v, w67.y);
                            }
                        }
                    }
                } else {
                    int sel[5];
                    bool okw[5];
#pragma unroll
                    for (int wq = 0; wq < 5; wq++) {
                        int zz = z0 - 1 + wq;
                        okw[wq] = ((unsigned)zz < (unsigned)HH);
                        sel[wq] = (zz == 0) ? 1 : ((zz == HH-1) ? 2 : 0);
                    }
                    for (int ic = 0; ic < 18; ic++) {
                        const float* cp = cbase + ic*H3 + base;
                        unsigned long long vp[5];
#pragma unroll
                        for (int wq = 0; wq < 5; wq++) {
                            float f = okw[wq] ? cp[wq - 1] : 0.f;
                            vp[wq] = pk2(f, f);
                        }
#pragma unroll
                        for (int dz = 0; dz < 3; dz++) {
#pragma unroll
                            for (int pp = 0; pp < 3; pp++) {
                                int wq = pp + dz;
                                const ulonglong2* wp = reinterpret_cast<const ulonglong2*>(
                                    ws + sel[wq]*WC1_PACK + (tap0+dz)*288 + (ic << 4));
                                ulonglong2 w01 = wp[0], w23 = wp[1], w45 = wp[2], w67 = wp[3];
                                unsigned long long v = vp[wq];
                                fma2(acc2[pp][0], v, w01.x); fma2(acc2[pp][1], v, w01.y);
                                fma2(acc2[pp][2], v, w23.x); fma2(acc2[pp][3], v, w23.y);
                                fma2(acc2[pp][4], v, w45.x); fma2(acc2[pp][5], v, w45.y);
                                fma2(acc2[pp][6], v, w67.x); fma2(acc2[pp][7], v, w67.y);
                            }
                        }
                    }
                }
            }
        }
    }

    int p0 = (x*HH + y)*HH + z0;
    int warp = threadIdx.x >> 5;
#pragma unroll
    for (int j = 0; j < 8; j++) {
        float sLo = 0.f, s2Lo = 0.f, sHi = 0.f, s2Hi = 0.f;
#pragma unroll
        for (int pp = 0; pp < 3; pp++) {
            float lo, hi;
            upk2(acc2[pp][j], lo, hi);
            if (valid) {
                g_c1[(n*16 + 2*j    )*H3 + p0 + pp] = lo;
                g_c1[(n*16 + 2*j + 1)*H3 + p0 + pp] = hi;
                sLo += lo; s2Lo += lo*lo;
                sHi += hi; s2Hi += hi*hi;
            }
        }
        float a = wred(sLo), b = wred(s2Lo);
        float c = wred(sHi), d = wred(s2Hi);
        if ((threadIdx.x & 31) == 0) {
            sW[warp][2*j  ][0] = (double)a; sW[warp][2*j  ][1] = (double)b;
            sW[warp][2*j+1][0] = (double)c; sW[warp][2*j+1][1] = (double)d;
        }
        __syncwarp();
    }
    __syncthreads();
    if (threadIdx.x < 16) {
        double s = 0.0, s2 = 0.0;
        for (int wi = 0; wi < 8; wi++) { s += sW[wi][threadIdx.x][0]; s2 += sW[wi][threadIdx.x][1]; }
        g_pc1[(threadIdx.x*NBLK1 + blockIdx.x)*2 + 0] = s;
        g_pc1[(threadIdx.x*NBLK1 + blockIdx.x)*2 + 1] = s2;
    }
}

// ---------------- stats reduce: per-channel partial sums -> mean/istd ----------------
__global__ void stats_reduce(int phase) {
    int ch = blockIdx.x;
    int NP = phase ? NBLK2 : NBLK1;
    const double* src = phase ? g_pc2 : g_pc1;
    __shared__ double sh[256], sh2[256];
    double s = 0.0, s2 = 0.0;
    for (int i = threadIdx.x; i < NP; i += 256) {
        s  += src[(ch*NP + i)*2 + 0];
        s2 += src[(ch*NP + i)*2 + 1];
    }
    sh[threadIdx.x] = s; sh2[threadIdx.x] = s2;
    __syncthreads();
    for (int st = 128; st > 0; st >>= 1) {
        if (threadIdx.x < st) { sh[threadIdx.x] += sh[threadIdx.x+st]; sh2[threadIdx.x] += sh2[threadIdx.x+st]; }
        __syncthreads();
    }
    if (threadIdx.x == 0) {
        double total = (double)NB * (phase ? S3 : H3);
        double mean = sh[0] / total;
        double var  = sh2[0] / total - mean*mean;
        g_stat[phase*32 + ch]      = (float)mean;
        g_stat[phase*32 + 16 + ch] = (float)(1.0 / sqrt(var + 1e-5));
    }
}

// ---------------- BN1 + relu + trilinear upsample x2 (align_corners) ----------------
__device__ __forceinline__ float bnrelu(float v, float sc, float sh) { return fmaxf(v*sc + sh, 0.f); }

__global__ void upsample_kernel(const float* __restrict__ g1p, const float* __restrict__ b1p,
                                const float* __restrict__ g1v, const float* __restrict__ b1v) {
    int idx = blockIdx.x * blockDim.x + threadIdx.x;
    if (idx >= NB*16*S3) return;
    int p = idx % S3; int ch = (idx / S3) % 16; int n = idx / (16*S3);
    int Z = p % S, Y = (p / S) % S, X = p / S2;

    float mean = g_stat[ch], istd = g_stat[16 + ch];
    float gg = (ch < 8) ? g1p[ch] : g1v[ch-8];
    float bb = (ch < 8) ? b1p[ch] : b1v[ch-8];
    float sc = istd * gg, sh = bb - mean * sc;

    const float SC = 32.f / 65.f;
    float sx = X * SC; int x0 = (int)sx; float fx = sx - x0; int x1 = min(x0+1, 32);
    float sy = Y * SC; int y0 = (int)sy; float fy = sy - y0; int y1 = min(y0+1, 32);
    float sz = Z * SC; int z0 = (int)sz; float fz = sz - z0; int z1 = min(z0+1, 32);

    const float* base = g_c1 + (n*16 + ch)*H3;
#define RD(xi,yi,zi) bnrelu(base[((xi)*HH+(yi))*HH+(zi)], sc, sh)
    float v =
      ((RD(x0,y0,z0)*(1-fx) + RD(x1,y0,z0)*fx)*(1-fy) + (RD(x0,y1,z0)*(1-fx) + RD(x1,y1,z0)*fx)*fy)*(1-fz)
    + ((RD(x0,y0,z1)*(1-fx) + RD(x1,y0,z1)*fx)*(1-fy) + (RD(x0,y1,z1)*(1-fx) + RD(x1,y1,z1)*fx)*fy)*fz;
#undef RD
    g_u1[idx] = v;
}

// ---------------- conv2: grouped 2x(8->8), z-vec x3, f32x2, fused BN stat partials ----------------
__global__ void conv2_kernel() {
    __shared__ __align__(16) float ws[27*8*16];
    __shared__ double sW[8][16][2];
    for (int i = threadIdx.x; i < 27*8*16; i += blockDim.x) ws[i] = g_wp2[i];
    __syncthreads();

    int idx = blockIdx.x * blockDim.x + threadIdx.x;
    bool valid = (idx < NB*S*S*22);
    int zt = 0, y = 0, x = 0, n = 0;
    if (valid) {
        zt = idx % 22;
        y  = (idx / 22) % S;
        x  = (idx / (22*S)) % S;
        n  = idx / (22*S*S);
    }
    int z0 = 3*zt;

    unsigned long long acc2[3][8];
#pragma unroll
    for (int pp = 0; pp < 3; pp++)
#pragma unroll
        for (int i = 0; i < 8; i++) acc2[pp][i] = 0ULL;

    if (valid) {
        const float* ubase = g_u1 + n*16*S3;
        bool zlo = (zt == 0);
        bool zhi = (zt == 21);

#pragma unroll
        for (int dx = -1; dx <= 1; dx++) {
            int xx = x + dx;
            if ((unsigned)xx >= (unsigned)S) continue;
#pragma unroll
            for (int dy = -1; dy <= 1; dy++) {
                int yy = y + dy;
                if ((unsigned)yy >= (unsigned)S) continue;
                int tap0 = ((dx+1)*3 + (dy+1))*3;
                const float* col = ubase + (xx*S + yy)*S + z0;
#pragma unroll
                for (int icg = 0; icg < 8; icg++) {
                    const float* cp = col + icg*S3;
                    const float* cv = col + (8+icg)*S3;
                    float inp[5], inv[5];
                    inp[0] = zlo ? 0.f : cp[-1];  inv[0] = zlo ? 0.f : cv[-1];
                    inp[1] = cp[0];               inv[1] = cv[0];
                    inp[2] = cp[1];               inv[2] = cv[1];
                    inp[3] = cp[2];               inv[3] = cv[2];
                    inp[4] = zhi ? 0.f : cp[3];   inv[4] = zhi ? 0.f : cv[3];
                    unsigned long long ip2[5], iv2[5];
#pragma unroll
                    for (int t = 0; t < 5; t++) { ip2[t] = pk2(inp[t], inp[t]); iv2[t] = pk2(inv[t], inv[t]); }
#pragma unroll
                    for (int dz = 0; dz < 3; dz++) {
                        const ulonglong2* wp =
                            reinterpret_cast<const ulonglong2*>(ws + (((tap0+dz)*8 + icg) << 4));
                        ulonglong2 w01 = wp[0], w23 = wp[1], w45 = wp[2], w67 = wp[3];
#pragma unroll
                        for (int pp = 0; pp < 3; pp++) {
                            unsigned long long vp = ip2[pp+dz];
                            unsigned long long vv = iv2[pp+dz];
                            fma2(acc2[pp][0], vp, w01.x); fma2(acc2[pp][1], vp, w01.y);
                            fma2(acc2[pp][2], vp, w23.x); fma2(acc2[pp][3], vp, w23.y);
                            fma2(acc2[pp][4], vv, w45.x); fma2(acc2[pp][5], vv, w45.y);
                            fma2(acc2[pp][6], vv, w67.x); fma2(acc2[pp][7], vv, w67.y);
                        }
                    }
                }
            }
        }
    }

    int ob = (x*S + y)*S + z0;
    int warp = threadIdx.x >> 5;
#pragma unroll
    for (int j = 0; j < 8; j++) {
        float sLo = 0.f, s2Lo = 0.f, sHi = 0.f, s2Hi = 0.f;
#pragma unroll
        for (int pp = 0; pp < 3; pp++) {
            float lo, hi;
            upk2(acc2[pp][j], lo, hi);
            if (valid) {
                g_c2[(n*16 + 2*j    )*S3 + ob + pp] = lo;
                g_c2[(n*16 + 2*j + 1)*S3 + ob + pp] = hi;
                sLo += lo; s2Lo += lo*lo;
                sHi += hi; s2Hi += hi*hi;
            }
        }
        float a = wred(sLo), b = wred(s2Lo);
        float c = wred(sHi), d = wred(s2Hi);
        if ((threadIdx.x & 31) == 0) {
            sW[warp][2*j  ][0] = (double)a; sW[warp][2*j  ][1] = (double)b;
            sW[warp][2*j+1][0] = (double)c; sW[warp][2*j+1][1] = (double)d;
        }
        __syncwarp();
    }
    __syncthreads();
    if (threadIdx.x < 16) {
        double s = 0.0, s2 = 0.0;
        for (int wi = 0; wi < 8; wi++) { s += sW[wi][threadIdx.x][0]; s2 += sW[wi][threadIdx.x][1]; }
        g_pc2[(threadIdx.x*NBLK2 + blockIdx.x)*2 + 0] = s;
        g_pc2[(threadIdx.x*NBLK2 + blockIdx.x)*2 + 1] = s2;
    }
}

// ---------------- BN2 + relu + 1x1 heads -> helmholtz (into d_out) ----------------
__global__ void helm_kernel(const float* __restrict__ g2p, const float* __restrict__ b2p,
                            const float* __restrict__ g2v, const float* __restrict__ b2v,
                            const float* __restrict__ pow_, const float* __restrict__ pob,
                            const float* __restrict__ vow,  const float* __restrict__ vob,
                            const float* __restrict__ phiw, const float* __restrict__ vortw,
                            float* __restrict__ out) {
    int idx = blockIdx.x * blockDim.x + threadIdx.x;
    if (idx >= NB*S3) return;
    int p = idx % S3; int n = idx / S3;

    float y[16];
#pragma unroll
    for (int c = 0; c < 16; c++) {
        float mean = g_stat[32 + c], istd = g_stat[48 + c];
        float gg = (c < 8) ? g2p[c] : g2v[c-8];
        float bb = (c < 8) ? b2p[c] : b2v[c-8];
        float v = (g_c2[(n*16 + c)*S3 + p] - mean) * istd * gg + bb;
        y[c] = fmaxf(v, 0.f);
    }
    float ph = pob[0];
#pragma unroll
    for (int c = 0; c < 8; c++) ph += y[c] * pow_[c];
    ph *= phiw[0];
    out[OFF_HELM + (n*4)*S3 + p] = ph;
    float vscale = vortw[0] * 66.f;
#pragma unroll
    for (int r = 0; r < 3; r++) {
        float v = vob[r];
#pragma unroll
        for (int c = 0; c < 8; c++) v += y[8+c] * vow[r*8 + c];
        out[OFF_HELM + (n*4 + 1 + r)*S3 + p] = v * vscale;
    }
}

// ---------------- velocity stencils (into d_out) ----------------
__device__ __forceinline__ float HV(const float* hm, int ch, int x, int y, int z) {
    return hm[ch*S3 + (x*S + y)*S + z];
}

__global__ void vel_kernel(float* __restrict__ out) {
    int idx = blockIdx.x * blockDim.x + threadIdx.x;
    if (idx >= NB*D3) return;
    int p = idx % D3; int n = idx / D3;
    int k = p & 63, j = (p >> 6) & 63, i = p >> 12;
    const float* hm = out + OFF_HELM + n*4*S3;

    float vp0 = 0.5f * (HV(hm,0, 1+i, 1+j, k+2) - HV(hm,0, 1+i, 1+j, k));
    float vp1 = 0.5f * (HV(hm,0, 1+i, j+2, 1+k) - HV(hm,0, 1+i, j,   1+k));
    float vp2 = 0.5f * (HV(hm,0, i+2, 1+j, 1+k) - HV(hm,0, i,   1+j, 1+k));

    float ua = (HV(hm,2, 2+i,1+j,k+1) - HV(hm,2, 1+i,1+j,k+1)) - (HV(hm,1, 1+i,2+j,k+1) - HV(hm,1, 1+i,1+j,k+1));
    float ub = (HV(hm,2, 2+i,1+j,k  ) - HV(hm,2, 1+i,1+j,k  )) - (HV(hm,1, 1+i,2+j,k  ) - HV(hm,1, 1+i,1+j,k  ));
    float vv0 = 0.5f * (ua + ub);
    float va = (HV(hm,1, 1+i,j+1,k+2) - HV(hm,1, 1+i,j+1,k+1)) - (HV(hm,3, i+2,j+1,k+1) - HV(hm,3, i+1,j+1,k+1));
    float vb = (HV(hm,1, 1+i,j,  k+2) - HV(hm,1, 1+i,j,  k+1)) - (HV(hm,3, i+2,j,  k+1) - HV(hm,3, i+1,j,  k+1));
    float vv1 = 0.5f * (va + vb);
    float wa = (HV(hm,3, i+1,j+2,k+1) - HV(hm,3, i+1,j+1,k+1)) - (HV(hm,2, i+1,j+1,k+2) - HV(hm,2, i+1,j+1,k+1));
    float wb = (HV(hm,3, i,  j+2,k+1) - HV(hm,3, i,  j+1,k+1)) - (HV(hm,2, i,  j+1,k+2) - HV(hm,2, i,  j+1,k+1));
    float vv2 = 0.5f * (wa + wb);

    int b = n*3*D3 + p;
    out[OFF_VPHI  + b        ] = vp0;
    out[OFF_VPHI  + b + D3   ] = vp1;
    out[OFF_VPHI  + b + 2*D3 ] = vp2;
    out[OFF_VVORT + b        ] = vv0;
    out[OFF_VVORT + b + D3   ] = vv1;
    out[OFF_VVORT + b + 2*D3 ] = vv2;
    out[OFF_VEL   + b        ] = vp0 + vv0;
    out[OFF_VEL   + b + D3   ] = vp1 + vv1;
    out[OFF_VEL   + b + 2*D3 ] = vp2 + vv2;
}

// ---------------- BFECC advect passes ----------------
__global__ void advect_kernel(const float* __restrict__ ext_src, const float* __restrict__ tex,
                              const float* __restrict__ vel, float sgn, int mode) {
    int idx = blockIdx.x * blockDim.x + threadIdx.x;
    if (idx >= NB*D3) return;
    int p = idx % D3; int n = idx / D3;
    int k = p & 63, j = (p >> 6) & 63, i = p >> 12;

    float v0 = vel[(n*3    )*D3 + p];
    float v1 = vel[(n*3 + 1)*D3 + p];
    float v2 = vel[(n*3 + 2)*D3 + p];
    float px = (float)i - sgn*v2;
    float py = (float)j - sgn*v1;
    float pz = (float)k - sgn*v0;
    px = fminf(fmaxf(px, 0.f), 63.f);
    py = fminf(fmaxf(py, 0.f), 63.f);
    pz = fminf(fmaxf(pz, 0.f), 63.f);
    int x0 = (int)px; float fx = px - x0; int x1 = min(x0+1, 63);
    int y0 = (int)py; float fy = py - y0; int y1 = min(y0+1, 63);
    int z0 = (int)pz; float fz = pz - z0; int z1 = min(z0+1, 63);

    float w000 = (1-fx)*(1-fy)*(1-fz), w001 = (1-fx)*(1-fy)*fz;
    float w010 = (1-fx)*fy*(1-fz),     w011 = (1-fx)*fy*fz;
    float w100 = fx*(1-fy)*(1-fz),     w101 = fx*(1-fy)*fz;
    float w110 = fx*fy*(1-fz),         w111 = fx*fy*fz;

    int b00 = (x0*64 + y0)*64, b01 = (x0*64 + y1)*64;
    int b10 = (x1*64 + y0)*64, b11 = (x1*64 + y1)*64;

    const float* src = (mode == 0) ? ext_src : ((mode == 1) ? g_phi1 : g_comb);
    float* dst = (mode == 0) ? g_phi1 : ((mode == 1) ? g_comb : g_pred);

#pragma unroll
    for (int c = 0; c < 8; c++) {
        const float* s = src + (n*8 + c)*D3;
        float v = w000*s[b00+z0] + w001*s[b00+z1] + w010*s[b01+z0] + w011*s[b01+z1]
                + w100*s[b10+z0] + w101*s[b10+z1] + w110*s[b11+z0] + w111*s[b11+z1];
        if (mode == 1) v = 1.5f * tex[(n*8 + c)*D3 + p] - 0.5f * v;
        dst[(n*8 + c)*D3 + p] = v;
    }
}

// ---------------- fused LN + FF (LN, @W1+b1, GELU, @W2+b2, residual -> d_out) ----------------
__global__ void ff_kernel(const float* __restrict__ lng, const float* __restrict__ lnb,
                          const float* __restrict__ w1, const float* __restrict__ b1,
                          const float* __restrict__ w2, const float* __restrict__ b2,
                          float* __restrict__ out) {
    __shared__ __align__(16) unsigned long long Wp1[2048];
    __shared__ __align__(16) unsigned long long Wp2[2048];
    __shared__ float Bv1[64], Bv2[64], G[64], Bt[64];
    float* fW1 = reinterpret_cast<float*>(Wp1);
    float* fW2 = reinterpret_cast<float*>(Wp2);
    for (int i = threadIdx.x; i < 4096; i += blockDim.x) {
        int ii = i >> 6, jj = i & 63;
        int d = (jj*32 + (ii >> 1))*2 + (ii & 1);
        fW1[d] = w1[i];
        fW2[d] = w2[i];
    }
    if (threadIdx.x < 64) {
        Bv1[threadIdx.x] = b1[threadIdx.x]; Bv2[threadIdx.x] = b2[threadIdx.x];
        G[threadIdx.x] = lng[threadIdx.x];  Bt[threadIdx.x] = lnb[threadIdx.x];
    }
    __syncthreads();

    int p = blockIdx.x * blockDim.x + threadIdx.x;
    if (p >= D3) return;

    float h[64]; float s = 0.f, s2 = 0.f;
#pragma unroll
    for (int c = 0; c < 64; c++) { float v = g_pred[c*D3 + p]; h[c] = v; s += v; s2 += v*v; }
    float mean = s * (1.f/64.f);
    float var  = s2 * (1.f/64.f) - mean*mean;
    float is = rsqrtf(var + 1e-5f);
    unsigned long long hp[32];
#pragma unroll
    for (int c = 0; c < 32; c++) {
        float e = (h[2*c]   - mean) * is * G[2*c]   + Bt[2*c];
        float o = (h[2*c+1] - mean) * is * G[2*c+1] + Bt[2*c+1];
        hp[c] = pk2(e, o);
    }

    unsigned long long gp[32];
    for (int jj = 0; jj < 64; jj += 2) {
        const ulonglong2* wrA = reinterpret_cast<const ulonglong2*>(Wp1 + jj*32);
        const ulonglong2* wrB = reinterpret_cast<const ulonglong2*>(Wp1 + (jj+1)*32);
        unsigned long long a0 = 0ULL, a1 = 0ULL, c0 = 0ULL, c1 = 0ULL;
#pragma unroll
        for (int q = 0; q < 16; q++) {
            ulonglong2 wa = wrA[q];
            ulonglong2 wb = wrB[q];
            fma2(a0, hp[2*q],   wa.x);
            fma2(a1, hp[2*q+1], wa.y);
            fma2(c0, hp[2*q],   wb.x);
            fma2(c1, hp[2*q+1], wb.y);
        }
        float l0, h0, l1, h1;
        upk2(a0, l0, h0); upk2(a1, l1, h1);
        float aA = Bv1[jj] + ((l0 + h0) + (l1 + h1));
        upk2(c0, l0, h0); upk2(c1, l1, h1);
        float aB = Bv1[jj+1] + ((l0 + h0) + (l1 + h1));
        float gA = 0.5f * aA * (1.f + erff(aA * 0.70710678118f));
        float gB = 0.5f * aB * (1.f + erff(aB * 0.70710678118f));
        gp[jj >> 1] = pk2(gA, gB);
    }

    for (int jj = 0; jj < 64; jj++) {
        const ulonglong2* wr = reinterpret_cast<const ulonglong2*>(Wp2 + jj*32);
        unsigned long long a0 = 0ULL, a1 = 0ULL;
#pragma unroll
        for (int q = 0; q < 16; q++) {
            ulonglong2 w2v = wr[q];
            fma2(a0, gp[2*q],   w2v.x);
            fma2(a1, gp[2*q+1], w2v.y);
        }
        float l0, h0, l1, h1;
        upk2(a0, l0, h0); upk2(a1, l1, h1);
        float a = Bv2[jj] + ((l0 + h0) + (l1 + h1));
        out[OFF_X + jj*D3 + p] = g_pred[jj*D3 + p] + a;
    }
}

// ---------------- host launch ----------------
extern "C" void kernel_launch(void* const* d_in, const int* in_sizes, int n_in,
                              void* d_out, int out_size) {
    const float* prev      = (const float*)d_in[0];
    const float* nxt       = (const float*)d_in[1];
    const float* texture   = (const float*)d_in[2];
    const float* mask      = (const float*)d_in[3];
    const float* boundary  = (const float*)d_in[4];
    const float* enc_w     = (const float*)d_in[5];
    const float* enc_b     = (const float*)d_in[6];
    const float* phi_c1_w  = (const float*)d_in[7];
    const float* phi_bn1_g = (const float*)d_in[8];
    const float* phi_bn1_b = (const float*)d_in[9];
    const float* phi_c2_w  = (const float*)d_in[10];
    const float* phi_bn2_g = (const float*)d_in[11];
    const float* phi_bn2_b = (const float*)d_in[12];
    const float* phi_out_w = (const float*)d_in[13];
    const float* phi_out_b = (const float*)d_in[14];
    const float* vort_c1_w = (const float*)d_in[15];
    const float* vort_bn1_g= (const float*)d_in[16];
    const float* vort_bn1_b= (const float*)d_in[17];
    const float* vort_c2_w = (const float*)d_in[18];
    const float* vort_bn2_g= (const float*)d_in[19];
    const float* vort_bn2_b= (const float*)d_in[20];
    const float* vort_out_w= (const float*)d_in[21];
    const float* vort_out_b= (const float*)d_in[22];
    const float* phi_weight= (const float*)d_in[23];
    const float* vort_weight=(const float*)d_in[24];
    const float* ln_g      = (const float*)d_in[25];
    const float* ln_b      = (const float*)d_in[26];
    const float* ff_w1     = (const float*)d_in[27];
    const float* ff_b1     = (const float*)d_in[28];
    const float* ff_w2     = (const float*)d_in[29];
    const float* ff_b2     = (const float*)d_in[30];
    float* out = (float*)d_out;

    pack_kernel<<<(3*WC1_PACK + 255)/256, 256>>>(phi_c1_w, vort_c1_w, phi_c2_w, vort_c2_w);

    int encBlocks = NB * ENC_BPN;
    enc_kernel<<<encBlocks, 256>>>(prev, mask,     enc_w, enc_b, 0);
    enc_kernel<<<encBlocks, 256>>>(prev, boundary, enc_w, enc_b, 1);
    enc_kernel<<<encBlocks, 256>>>(nxt,  mask,     enc_w, enc_b, 2);

    corr_kernel<<<(NB*H3 + 255)/256, 256>>>();

    cudaFuncSetAttribute(conv1_kernel, cudaFuncAttributeMaxDynamicSharedMemorySize, 3*WC1_PACK*4);
    conv1_kernel<<<NBLK1, 256, 3*WC1_PACK*4>>>();
    stats_reduce<<<16, 256>>>(0);

    int upN = NB*16*S3;
    upsample_kernel<<<(upN + 255)/256, 256>>>(phi_bn1_g, phi_bn1_b, vort_bn1_g, vort_bn1_b);

    conv2_kernel<<<NBLK2, 256>>>();
    stats_reduce<<<16, 256>>>(1);

    helm_kernel<<<(NB*S3 + 255)/256, 256>>>(phi_bn2_g, phi_bn2_b, vort_bn2_g, vort_bn2_b,
                                            phi_out_w, phi_out_b, vort_out_w, vort_out_b,
                                            phi_weight, vort_weight, out);

    vel_kernel<<<(NB*D3 + 255)/256, 256>>>(out);

    const float* vel = out + OFF_VEL;
    advect_kernel<<<(NB*D3 + 255)/256, 256>>>(texture, texture, vel,  1.f, 0);
    advect_kernel<<<(NB*D3 + 255)/256, 256>>>(texture, texture, vel, -1.f, 1);
    advect_kernel<<<(NB*D3 + 255)/256, 256>>>(texture, texture, vel,  1.f, 2);

    ff_kernel<<<(D3 + 127)/128, 128>>>(ln_g, ln_b, ff_w1, ff_b1, ff_w2, ff_b2, out);
}